// round 1
// baseline (speedup 1.0000x reference)
#include <cuda_runtime.h>
#include <math.h>

#define Bdim 2
#define Tdim 4096
#define Cdim 2048
#define Hdim 64
#define Nheads 32
#define BT   (Bdim*Tdim)            // 8192
#define BTC  (Bdim*Tdim*Cdim)       // 16777216
#define BNHH (Bdim*Nheads*Hdim*Hdim) // 262144

// ---------------- scratch (module-load allocated, no cudaMalloc) ----------------
__device__ float g_dxprev[BTC];
__device__ float g_xmix[BTC];
__device__ float g_xr[BTC];
__device__ float g_xk[BTC];
__device__ float g_xv[BTC];
__device__ float g_xw[BTC];
__device__ float g_xv2[BTC];
__device__ float g_r[BTC];
__device__ float g_k[BTC];
__device__ float g_v[BTC];
__device__ float g_v2[BTC];
__device__ float g_w[BTC];
__device__ float g_y[BTC];
__device__ float g_xxx[BT*160];
__device__ float g_h[BT*64];

// ---------------- 1. token shift + base mix ----------------
__global__ void prep_kernel(const float* __restrict__ x,
                            const float* __restrict__ shift,
                            const float* __restrict__ maa_x) {
    long idx = (long)blockIdx.x * 256 + threadIdx.x;
    int c = (int)(idx & (Cdim - 1));
    long tc = idx % ((long)Tdim * Cdim);
    float prev;
    if (tc < Cdim) {  // t == 0
        long b = idx / ((long)Tdim * Cdim);
        prev = shift[b * Cdim + c];
    } else {
        prev = x[idx - Cdim];
    }
    float xc = x[idx];
    float dx = prev - xc;
    g_dxprev[idx] = dx;
    g_xmix[idx] = xc + dx * maa_x[c];
}

// ---------------- 2. xxx = tanh(xmix @ maa_w1)  [8192,2048]x[2048,160] ----------------
__global__ __launch_bounds__(256) void xxx_kernel(const float* __restrict__ w1) {
    __shared__ float sa[4][Cdim];
    int m0 = blockIdx.x * 4;
    int tid = threadIdx.x;
    for (int i = tid; i < 4 * Cdim; i += 256)
        sa[i >> 11][i & (Cdim - 1)] = g_xmix[(long)(m0 + (i >> 11)) * Cdim + (i & (Cdim - 1))];
    __syncthreads();
    if (tid < 160) {
        int j = tid;
        float a0 = 0.f, a1 = 0.f, a2 = 0.f, a3 = 0.f;
        for (int k = 0; k < Cdim; k++) {
            float w = w1[k * 160 + j];
            a0 += sa[0][k] * w;
            a1 += sa[1][k] * w;
            a2 += sa[2][k] * w;
            a3 += sa[3][k] * w;
        }
        g_xxx[(m0 + 0) * 160 + j] = tanhf(a0);
        g_xxx[(m0 + 1) * 160 + j] = tanhf(a1);
        g_xxx[(m0 + 2) * 160 + j] = tanhf(a2);
        g_xxx[(m0 + 3) * 160 + j] = tanhf(a3);
    }
}

// ---------------- 3. mix coefficients -> xr,xk,xv,xw,xv2 ----------------
__global__ __launch_bounds__(256) void mixout_kernel(
    const float* __restrict__ x,
    const float* __restrict__ maa_r, const float* __restrict__ maa_k,
    const float* __restrict__ maa_v, const float* __restrict__ maa_w,
    const float* __restrict__ maa_v2, const float* __restrict__ w2) {
    __shared__ float sx[4][160];
    int m0 = blockIdx.x * 4;
    int tid = threadIdx.x;
    for (int i = tid; i < 4 * 160; i += 256)
        sx[i / 160][i % 160] = g_xxx[(m0 + i / 160) * 160 + (i % 160)];
    __syncthreads();
    for (int c = tid; c < Cdim; c += 256) {
        float mr = maa_r[c], mk = maa_k[c], mv = maa_v[c], mw = maa_w[c], mv2 = maa_v2[c];
        float acc[4][5];
        #pragma unroll
        for (int r = 0; r < 4; r++)
            #pragma unroll
            for (int f = 0; f < 5; f++) acc[r][f] = 0.f;
        for (int f = 0; f < 5; f++) {
            #pragma unroll 8
            for (int l = 0; l < 32; l++) {
                float wv = w2[(f * 32 + l) * Cdim + c];
                #pragma unroll
                for (int r = 0; r < 4; r++) acc[r][f] += sx[r][f * 32 + l] * wv;
            }
        }
        #pragma unroll
        for (int r = 0; r < 4; r++) {
            long idx = (long)(m0 + r) * Cdim + c;
            float xc = x[idx];
            float dx = g_dxprev[idx];
            g_xr[idx]  = xc + dx * (mr  + acc[r][0]);
            g_xk[idx]  = xc + dx * (mk  + acc[r][1]);
            g_xv[idx]  = xc + dx * (mv  + acc[r][2]);
            g_xw[idx]  = xc + dx * (mw  + acc[r][3]);
            g_xv2[idx] = xc + dx * (mv2 + acc[r][4]);
        }
    }
}

// ---------------- 4. big NT GEMM: C[m][n] = sum_k A[m][k]*B[n][k] ----------------
// M=8192, N=2048, K=2048 (all multiples of tile; no bounds checks)
#define GBM 128
#define GBN 128
#define GBK 8
__global__ __launch_bounds__(256) void sgemm_nt(const float* __restrict__ A,
                                                const float* __restrict__ B,
                                                float* __restrict__ C,
                                                int M, int N, int K) {
    __shared__ float As[GBK][GBM + 4];
    __shared__ float Bs[GBK][GBN + 4];
    int bm = blockIdx.y * GBM;
    int bn = blockIdx.x * GBN;
    int tid = threadIdx.x;
    int lrow = tid >> 1;
    int lcol = (tid & 1) * 4;
    int tr = tid >> 4;     // 0..15
    int tc = tid & 15;     // 0..15
    float acc[8][8];
    #pragma unroll
    for (int i = 0; i < 8; i++)
        #pragma unroll
        for (int j = 0; j < 8; j++) acc[i][j] = 0.f;

    const float* Ap = A + (long)(bm + lrow) * K + lcol;
    const float* Bp = B + (long)(bn + lrow) * K + lcol;

    for (int k0 = 0; k0 < K; k0 += GBK) {
        float4 a4 = *(const float4*)(Ap + k0);
        float4 b4 = *(const float4*)(Bp + k0);
        As[lcol + 0][lrow] = a4.x; As[lcol + 1][lrow] = a4.y;
        As[lcol + 2][lrow] = a4.z; As[lcol + 3][lrow] = a4.w;
        Bs[lcol + 0][lrow] = b4.x; Bs[lcol + 1][lrow] = b4.y;
        Bs[lcol + 2][lrow] = b4.z; Bs[lcol + 3][lrow] = b4.w;
        __syncthreads();
        #pragma unroll
        for (int kk = 0; kk < GBK; kk++) {
            float ra[8], rb[8];
            #pragma unroll
            for (int i = 0; i < 8; i++) ra[i] = As[kk][tr * 8 + i];
            #pragma unroll
            for (int j = 0; j < 8; j++) rb[j] = Bs[kk][tc * 8 + j];
            #pragma unroll
            for (int i = 0; i < 8; i++)
                #pragma unroll
                for (int j = 0; j < 8; j++) acc[i][j] += ra[i] * rb[j];
        }
        __syncthreads();
    }
    #pragma unroll
    for (int i = 0; i < 8; i++) {
        float* cp = C + (long)(bm + tr * 8 + i) * N + bn + tc * 8;
        float4 o0 = make_float4(acc[i][0], acc[i][1], acc[i][2], acc[i][3]);
        float4 o1 = make_float4(acc[i][4], acc[i][5], acc[i][6], acc[i][7]);
        *(float4*)cp = o0;
        *(float4*)(cp + 4) = o1;
    }
}

// ---------------- 5. LoRA stage 1: out = tanh(A @ W) , W:[2048][64] ----------------
__global__ __launch_bounds__(256) void lora1_kernel(const float* __restrict__ A,
                                                    const float* __restrict__ W) {
    __shared__ float sa[4][Cdim];
    int m0 = blockIdx.x * 4;
    int tid = threadIdx.x;
    for (int i = tid; i < 4 * Cdim; i += 256)
        sa[i >> 11][i & (Cdim - 1)] = A[(long)(m0 + (i >> 11)) * Cdim + (i & (Cdim - 1))];
    __syncthreads();
    int j = tid & 63;
    int r = tid >> 6;  // 0..3
    float s = 0.f;
    for (int k = 0; k < Cdim; k++) s += sa[r][k] * W[k * 64 + j];
    g_h[(m0 + r) * 64 + j] = tanhf(s);
}

// ---------------- 6. LoRA stage 2: out = base + h @ W2 , W2:[64][2048] ----------------
// accumulate==1: base = out[idx] (in place add); else base = biasvec[c]
__global__ __launch_bounds__(256) void lora2_kernel(const float* __restrict__ W2,
                                                    float* __restrict__ out,
                                                    const float* __restrict__ biasvec,
                                                    int accumulate) {
    __shared__ float sh[4][64];
    int m0 = blockIdx.x * 4;
    int tid = threadIdx.x;
    if (tid < 256)
        sh[tid >> 6][tid & 63] = g_h[(m0 + (tid >> 6)) * 64 + (tid & 63)];
    __syncthreads();
    for (int c = tid; c < Cdim; c += 256) {
        float s0 = 0.f, s1 = 0.f, s2 = 0.f, s3 = 0.f;
        #pragma unroll 8
        for (int l = 0; l < 64; l++) {
            float w = W2[l * Cdim + c];
            s0 += sh[0][l] * w;
            s1 += sh[1][l] * w;
            s2 += sh[2][l] * w;
            s3 += sh[3][l] * w;
        }
        float sv[4] = {s0, s1, s2, s3};
        #pragma unroll
        for (int r = 0; r < 4; r++) {
            long idx = (long)(m0 + r) * Cdim + c;
            float base = accumulate ? out[idx] : biasvec[c];
            out[idx] = base + sv[r];
        }
    }
}

// ---------------- 7. decay = exp(-exp(w)); k *= (1-decay) ----------------
__global__ void decayk_kernel() {
    long i = (long)blockIdx.x * 256 + threadIdx.x;
    float d = expf(-expf(g_w[i]));
    g_w[i] = d;
    g_k[i] *= (1.0f - d);
}

// ---------------- 8. WKV scan (one block per (b, head); thread = column j) ----------------
__global__ __launch_bounds__(64) void wkv_scan_kernel(const float* __restrict__ state0,
                                                      float* __restrict__ stateout) {
    int bn = blockIdx.x;          // 0..63
    int b = bn >> 5;              // /32
    int n = bn & 31;
    int j = threadIdx.x;

    float st[64];
    #pragma unroll
    for (int i = 0; i < 64; i++) st[i] = state0[((long)bn * 64 + i) * 64 + j];

    __shared__ float sr[64], sk[64], sd[64];

    long base = ((long)b * Tdim) * Cdim + n * 64;
    // prefetch t = 0
    float nr = g_r[base + j], nk = g_k[base + j], nd = g_w[base + j];
    float nv = g_v[base + j], nv2 = g_v2[base + j];

    for (int t = 0; t < Tdim; t++) {
        long nb = (t == Tdim - 1) ? base : base + Cdim;
        float cr = nr, ck = nk, cd = nd, cv = nv, cv2 = nv2;
        // prefetch next step (overlaps with compute below)
        nr = g_r[nb + j]; nk = g_k[nb + j]; nd = g_w[nb + j];
        nv = g_v[nb + j]; nv2 = g_v2[nb + j];

        sr[j] = cr; sk[j] = ck; sd[j] = cd;
        __syncthreads();

        float y0 = 0.f, y1 = 0.f, y2 = 0.f, y3 = 0.f;
        #pragma unroll
        for (int i = 0; i < 64; i += 4) {
            y0 += sr[i]     * st[i];
            y1 += sr[i + 1] * st[i + 1];
            y2 += sr[i + 2] * st[i + 2];
            y3 += sr[i + 3] * st[i + 3];
        }
        g_y[base + j] = ((y0 + y1) + (y2 + y3)) + cv2;

        #pragma unroll
        for (int i = 0; i < 64; i++) st[i] = st[i] * sd[i] + sk[i] * cv;
        __syncthreads();
        base = nb;
    }
    #pragma unroll
    for (int i = 0; i < 64; i++) stateout[((long)bn * 64 + i) * 64 + j] = st[i];
}

// ---------------- 9. layernorm on y -> g_xmix ----------------
__global__ __launch_bounds__(256) void ln_kernel(const float* __restrict__ g,
                                                 const float* __restrict__ bb) {
    __shared__ float red[256];
    int m = blockIdx.x, tid = threadIdx.x;
    const float* row = g_y + (long)m * Cdim;
    float s1 = 0.f, s2 = 0.f;
    for (int c = tid; c < Cdim; c += 256) {
        float v = row[c];
        s1 += v;
        s2 += v * v;
    }
    red[tid] = s1;
    __syncthreads();
    for (int s = 128; s > 0; s >>= 1) {
        if (tid < s) red[tid] += red[tid + s];
        __syncthreads();
    }
    float mu = red[0] * (1.0f / Cdim);
    __syncthreads();
    red[tid] = s2;
    __syncthreads();
    for (int s = 128; s > 0; s >>= 1) {
        if (tid < s) red[tid] += red[tid + s];
        __syncthreads();
    }
    float var = red[0] * (1.0f / Cdim) - mu * mu;
    float rs = rsqrtf(var + 1e-5f);
    for (int c = tid; c < Cdim; c += 256)
        g_xmix[(long)m * Cdim + c] = (row[c] - mu) * rs * g[c] + bb[c];
}

// ---------------- 10. tail: x[:, -1] ----------------
__global__ void tail_kernel(const float* __restrict__ x, float* __restrict__ out2) {
    int i = blockIdx.x * 256 + threadIdx.x;
    if (i < Bdim * Cdim) {
        int b = i / Cdim, c = i % Cdim;
        out2[i] = x[((long)b * Tdim + (Tdim - 1)) * Cdim + c];
    }
}

// ---------------- host ----------------
static float* sym(const void* symbol) {
    void* p = nullptr;
    cudaGetSymbolAddress(&p, symbol);
    return (float*)p;
}

extern "C" void kernel_launch(void* const* d_in, const int* in_sizes, int n_in,
                              void* d_out, int out_size) {
    const float* x       = (const float*)d_in[0];
    const float* wkv0    = (const float*)d_in[1];
    const float* shift   = (const float*)d_in[2];
    const float* maa_x   = (const float*)d_in[3];
    const float* maa_r   = (const float*)d_in[4];
    const float* maa_k   = (const float*)d_in[5];
    const float* maa_v   = (const float*)d_in[6];
    const float* maa_w   = (const float*)d_in[7];
    const float* maa_v2  = (const float*)d_in[8];
    const float* maa_w1  = (const float*)d_in[9];
    const float* maa_w2  = (const float*)d_in[10];
    const float* tdecay  = (const float*)d_in[11];
    const float* dec_w1  = (const float*)d_in[12];
    const float* dec_w2  = (const float*)d_in[13];
    const float* v2_w1   = (const float*)d_in[14];
    const float* v2_w2   = (const float*)d_in[15];
    const float* Wr      = (const float*)d_in[16];
    const float* Wk      = (const float*)d_in[17];
    const float* Wv      = (const float*)d_in[18];
    const float* Wo      = (const float*)d_in[19];
    const float* ln_g    = (const float*)d_in[20];
    const float* ln_b    = (const float*)d_in[21];
    float* out = (float*)d_out;

    float* p_xr  = sym(g_xr);
    float* p_xk  = sym(g_xk);
    float* p_xv  = sym(g_xv);
    float* p_xw  = sym(g_xw);
    float* p_xv2 = sym(g_xv2);
    float* p_r   = sym(g_r);
    float* p_k   = sym(g_k);
    float* p_v   = sym(g_v);
    float* p_v2  = sym(g_v2);
    float* p_w   = sym(g_w);
    float* p_xm  = sym(g_xmix);

    dim3 ggrid(Cdim / GBN, BT / GBM);  // (16, 64)

    prep_kernel<<<BTC / 256, 256>>>(x, shift, maa_x);
    xxx_kernel<<<BT / 4, 256>>>(maa_w1);
    mixout_kernel<<<BT / 4, 256>>>(x, maa_r, maa_k, maa_v, maa_w, maa_v2, maa_w2);

    sgemm_nt<<<ggrid, 256>>>(p_xr,  Wr, p_r,  BT, Cdim, Cdim);
    sgemm_nt<<<ggrid, 256>>>(p_xk,  Wk, p_k,  BT, Cdim, Cdim);
    sgemm_nt<<<ggrid, 256>>>(p_xv,  Wv, p_v,  BT, Cdim, Cdim);
    sgemm_nt<<<ggrid, 256>>>(p_xv2, Wv, p_v2, BT, Cdim, Cdim);

    lora1_kernel<<<BT / 4, 256>>>(p_xv2, v2_w1);
    lora2_kernel<<<BT / 4, 256>>>(v2_w2, p_v2, nullptr, 1);
    lora1_kernel<<<BT / 4, 256>>>(p_xw, dec_w1);
    lora2_kernel<<<BT / 4, 256>>>(dec_w2, p_w, tdecay, 0);

    decayk_kernel<<<BTC / 256, 256>>>();

    wkv_scan_kernel<<<Bdim * Nheads, 64>>>(wkv0, out + BTC);

    ln_kernel<<<BT, 256>>>(ln_g, ln_b);
    sgemm_nt<<<ggrid, 256>>>(p_xm, Wo, out, BT, Cdim, Cdim);

    tail_kernel<<<16, 256>>>(x, out + BTC + BNHH);
}

// round 2
// speedup vs baseline: 1.4662x; 1.4662x over previous
#include <cuda_runtime.h>
#include <math.h>
#include <stdint.h>

#define Bdim 2
#define Tdim 4096
#define Cdim 2048
#define Hdim 64
#define Nheads 32
#define BT   (Bdim*Tdim)            // 8192
#define BTC  (Bdim*Tdim*Cdim)       // 16777216
#define BNHH (Bdim*Nheads*Hdim*Hdim) // 262144

// ---------------- scratch (module-load allocated, no cudaMalloc) ----------------
__device__ float g_dxprev[BTC];
__device__ float g_xmix[BTC];
__device__ float g_xr[BTC];
__device__ float g_xk[BTC];
__device__ float g_xv[BTC];
__device__ float g_xw[BTC];
__device__ float g_xv2[BTC];
__device__ float g_r[BTC];
__device__ float g_k[BTC];
__device__ float g_v[BTC];
__device__ float g_v2[BTC];
__device__ float g_w[BTC];
__device__ float g_y[BTC];
__device__ float g_xxx[BT*160];
__device__ float g_h[BT*64];

// ---------------- helpers ----------------
__device__ __forceinline__ float f2tf32(float x) {
    uint32_t u;
    asm("cvt.rna.tf32.f32 %0, %1;" : "=r"(u) : "f"(x));
    return __uint_as_float(u);
}

__device__ __forceinline__ void mma_tf32(float* c, const uint32_t* a, const uint32_t* b) {
    asm volatile("mma.sync.aligned.m16n8k8.row.col.f32.tf32.tf32.f32 "
        "{%0,%1,%2,%3}, {%4,%5,%6,%7}, {%8,%9}, {%0,%1,%2,%3};"
        : "+f"(c[0]), "+f"(c[1]), "+f"(c[2]), "+f"(c[3])
        : "r"(a[0]), "r"(a[1]), "r"(a[2]), "r"(a[3]), "r"(b[0]), "r"(b[1]));
}

// ---------------- 1. token shift + base mix ----------------
__global__ void prep_kernel(const float* __restrict__ x,
                            const float* __restrict__ shift,
                            const float* __restrict__ maa_x) {
    long idx = (long)blockIdx.x * 256 + threadIdx.x;
    int c = (int)(idx & (Cdim - 1));
    long tc = idx % ((long)Tdim * Cdim);
    float prev;
    if (tc < Cdim) {  // t == 0
        long b = idx / ((long)Tdim * Cdim);
        prev = shift[b * Cdim + c];
    } else {
        prev = x[idx - Cdim];
    }
    float xc = x[idx];
    float dx = prev - xc;
    g_dxprev[idx] = dx;
    g_xmix[idx] = xc + dx * maa_x[c];
}

// ---------------- 2. xxx = tanh(xmix @ maa_w1)  [8192,2048]x[2048,160] ----------------
__global__ __launch_bounds__(256) void xxx_kernel(const float* __restrict__ w1) {
    __shared__ float sa[4][Cdim];
    int m0 = blockIdx.x * 4;
    int tid = threadIdx.x;
    for (int i = tid; i < 4 * Cdim; i += 256)
        sa[i >> 11][i & (Cdim - 1)] = g_xmix[(long)(m0 + (i >> 11)) * Cdim + (i & (Cdim - 1))];
    __syncthreads();
    if (tid < 160) {
        int j = tid;
        float a0 = 0.f, a1 = 0.f, a2 = 0.f, a3 = 0.f;
        for (int k = 0; k < Cdim; k++) {
            float w = w1[k * 160 + j];
            a0 += sa[0][k] * w;
            a1 += sa[1][k] * w;
            a2 += sa[2][k] * w;
            a3 += sa[3][k] * w;
        }
        g_xxx[(m0 + 0) * 160 + j] = tanhf(a0);
        g_xxx[(m0 + 1) * 160 + j] = tanhf(a1);
        g_xxx[(m0 + 2) * 160 + j] = tanhf(a2);
        g_xxx[(m0 + 3) * 160 + j] = tanhf(a3);
    }
}

// ---------------- 3. mix coefficients -> xr,xk,xv,xw,xv2 ----------------
__global__ __launch_bounds__(256) void mixout_kernel(
    const float* __restrict__ x,
    const float* __restrict__ maa_r, const float* __restrict__ maa_k,
    const float* __restrict__ maa_v, const float* __restrict__ maa_w,
    const float* __restrict__ maa_v2, const float* __restrict__ w2) {
    __shared__ float sx[4][160];
    int m0 = blockIdx.x * 4;
    int tid = threadIdx.x;
    for (int i = tid; i < 4 * 160; i += 256)
        sx[i / 160][i % 160] = g_xxx[(m0 + i / 160) * 160 + (i % 160)];
    __syncthreads();
    for (int c = tid; c < Cdim; c += 256) {
        float mr = maa_r[c], mk = maa_k[c], mv = maa_v[c], mw = maa_w[c], mv2 = maa_v2[c];
        float acc[4][5];
        #pragma unroll
        for (int r = 0; r < 4; r++)
            #pragma unroll
            for (int f = 0; f < 5; f++) acc[r][f] = 0.f;
        for (int f = 0; f < 5; f++) {
            #pragma unroll 8
            for (int l = 0; l < 32; l++) {
                float wv = w2[(f * 32 + l) * Cdim + c];
                #pragma unroll
                for (int r = 0; r < 4; r++) acc[r][f] += sx[r][f * 32 + l] * wv;
            }
        }
        #pragma unroll
        for (int r = 0; r < 4; r++) {
            long idx = (long)(m0 + r) * Cdim + c;
            float xc = x[idx];
            float dx = g_dxprev[idx];
            g_xr[idx]  = xc + dx * (mr  + acc[r][0]);
            g_xk[idx]  = xc + dx * (mk  + acc[r][1]);
            g_xv[idx]  = xc + dx * (mv  + acc[r][2]);
            g_xw[idx]  = xc + dx * (mw  + acc[r][3]);
            g_xv2[idx] = xc + dx * (mv2 + acc[r][4]);
        }
    }
}

// ---------------- 4. TF32 tensor-core NT GEMM ----------------
// C[m][n] = sum_k A[m][k] * B[n][k];  M=8192, N=2048, K=2048
#define TBM 128
#define TBN 128
#define TBK 16
#define TPAD 8
__global__ __launch_bounds__(256) void tgemm_nt(const float* __restrict__ A,
                                                const float* __restrict__ B,
                                                float* __restrict__ C,
                                                int M, int N, int K) {
    __shared__ float As[2][TBK][TBM + TPAD];
    __shared__ float Bs[2][TBK][TBN + TPAD];
    int tid = threadIdx.x;
    int bm = blockIdx.y * TBM, bn = blockIdx.x * TBN;
    int wid = tid >> 5, lane = tid & 31;
    int wm = (wid & 3) * 32;      // warp M offset
    int wn = (wid >> 2) * 64;     // warp N offset
    int g = lane >> 2, tg = lane & 3;

    // loader: thread handles rows lrow, lrow+64 at k-cols lk..lk+3
    int lrow = tid & 63;
    int lk = (tid >> 6) * 4;

    const float* Aptr = A + (long)(bm + lrow) * K + lk;
    const float* Bptr = B + (long)(bn + lrow) * K + lk;
    long rstride = (long)64 * K;

    float acc[2][8][4];
    #pragma unroll
    for (int i = 0; i < 2; i++)
        #pragma unroll
        for (int j = 0; j < 8; j++)
            #pragma unroll
            for (int q = 0; q < 4; q++) acc[i][j][q] = 0.f;

    float4 pa0, pa1, pb0, pb1;
    pa0 = *(const float4*)(Aptr);
    pa1 = *(const float4*)(Aptr + rstride);
    pb0 = *(const float4*)(Bptr);
    pb1 = *(const float4*)(Bptr + rstride);

    // store tile into buffer b (converts to tf32)
    #define STORE_TILE(bidx)                                                      \
        do {                                                                      \
            As[bidx][lk+0][lrow] = f2tf32(pa0.x);                                 \
            As[bidx][lk+1][lrow] = f2tf32(pa0.y);                                 \
            As[bidx][lk+2][lrow] = f2tf32(pa0.z);                                 \
            As[bidx][lk+3][lrow] = f2tf32(pa0.w);                                 \
            As[bidx][lk+0][lrow+64] = f2tf32(pa1.x);                              \
            As[bidx][lk+1][lrow+64] = f2tf32(pa1.y);                              \
            As[bidx][lk+2][lrow+64] = f2tf32(pa1.z);                              \
            As[bidx][lk+3][lrow+64] = f2tf32(pa1.w);                              \
            Bs[bidx][lk+0][lrow] = f2tf32(pb0.x);                                 \
            Bs[bidx][lk+1][lrow] = f2tf32(pb0.y);                                 \
            Bs[bidx][lk+2][lrow] = f2tf32(pb0.z);                                 \
            Bs[bidx][lk+3][lrow] = f2tf32(pb0.w);                                 \
            Bs[bidx][lk+0][lrow+64] = f2tf32(pb1.x);                              \
            Bs[bidx][lk+1][lrow+64] = f2tf32(pb1.y);                              \
            Bs[bidx][lk+2][lrow+64] = f2tf32(pb1.z);                              \
            Bs[bidx][lk+3][lrow+64] = f2tf32(pb1.w);                              \
        } while (0)

    #define COMPUTE_TILE(bidx)                                                    \
        do {                                                                      \
            _Pragma("unroll")                                                     \
            for (int kk = 0; kk < TBK; kk += 8) {                                 \
                uint32_t afr[2][4], bfr[8][2];                                    \
                _Pragma("unroll")                                                 \
                for (int i = 0; i < 2; i++) {                                     \
                    int r0 = wm + i * 16 + g;                                     \
                    afr[i][0] = __float_as_uint(As[bidx][kk+tg][r0]);             \
                    afr[i][1] = __float_as_uint(As[bidx][kk+tg][r0+8]);           \
                    afr[i][2] = __float_as_uint(As[bidx][kk+tg+4][r0]);           \
                    afr[i][3] = __float_as_uint(As[bidx][kk+tg+4][r0+8]);         \
                }                                                                 \
                _Pragma("unroll")                                                 \
                for (int j = 0; j < 8; j++) {                                     \
                    int c0 = wn + j * 8 + g;                                      \
                    bfr[j][0] = __float_as_uint(Bs[bidx][kk+tg][c0]);             \
                    bfr[j][1] = __float_as_uint(Bs[bidx][kk+tg+4][c0]);           \
                }                                                                 \
                _Pragma("unroll")                                                 \
                for (int i = 0; i < 2; i++)                                       \
                    _Pragma("unroll")                                             \
                    for (int j = 0; j < 8; j++)                                   \
                        mma_tf32(acc[i][j], afr[i], bfr[j]);                      \
            }                                                                     \
        } while (0)

    STORE_TILE(0);
    __syncthreads();

    int buf = 0;
    for (int k0 = TBK; k0 < K; k0 += TBK) {
        pa0 = *(const float4*)(Aptr + k0);
        pa1 = *(const float4*)(Aptr + rstride + k0);
        pb0 = *(const float4*)(Bptr + k0);
        pb1 = *(const float4*)(Bptr + rstride + k0);
        COMPUTE_TILE(buf);
        STORE_TILE(buf ^ 1);
        __syncthreads();
        buf ^= 1;
    }
    COMPUTE_TILE(buf);

    // epilogue
    #pragma unroll
    for (int i = 0; i < 2; i++) {
        #pragma unroll
        for (int j = 0; j < 8; j++) {
            int row = bm + wm + i * 16 + g;
            int col = bn + wn + j * 8 + tg * 2;
            float2* p0 = (float2*)(C + (long)row * N + col);
            float2* p1 = (float2*)(C + (long)(row + 8) * N + col);
            *p0 = make_float2(acc[i][j][0], acc[i][j][1]);
            *p1 = make_float2(acc[i][j][2], acc[i][j][3]);
        }
    }
    #undef STORE_TILE
    #undef COMPUTE_TILE
}

// ---------------- 5. LoRA stage 1: out = tanh(A @ W) , W:[2048][64] ----------------
__global__ __launch_bounds__(256) void lora1_kernel(const float* __restrict__ A,
                                                    const float* __restrict__ W) {
    __shared__ float sa[4][Cdim];
    int m0 = blockIdx.x * 4;
    int tid = threadIdx.x;
    for (int i = tid; i < 4 * Cdim; i += 256)
        sa[i >> 11][i & (Cdim - 1)] = A[(long)(m0 + (i >> 11)) * Cdim + (i & (Cdim - 1))];
    __syncthreads();
    int j = tid & 63;
    int r = tid >> 6;  // 0..3
    float s = 0.f;
    for (int k = 0; k < Cdim; k++) s += sa[r][k] * W[k * 64 + j];
    g_h[(m0 + r) * 64 + j] = tanhf(s);
}

// ---------------- 6. LoRA stage 2: out = base + h @ W2 , W2:[64][2048] ----------------
__global__ __launch_bounds__(256) void lora2_kernel(const float* __restrict__ W2,
                                                    float* __restrict__ out,
                                                    const float* __restrict__ biasvec,
                                                    int accumulate) {
    __shared__ float sh[4][64];
    int m0 = blockIdx.x * 4;
    int tid = threadIdx.x;
    if (tid < 256)
        sh[tid >> 6][tid & 63] = g_h[(m0 + (tid >> 6)) * 64 + (tid & 63)];
    __syncthreads();
    for (int c = tid; c < Cdim; c += 256) {
        float s0 = 0.f, s1 = 0.f, s2 = 0.f, s3 = 0.f;
        #pragma unroll 8
        for (int l = 0; l < 64; l++) {
            float w = W2[l * Cdim + c];
            s0 += sh[0][l] * w;
            s1 += sh[1][l] * w;
            s2 += sh[2][l] * w;
            s3 += sh[3][l] * w;
        }
        float sv[4] = {s0, s1, s2, s3};
        #pragma unroll
        for (int r = 0; r < 4; r++) {
            long idx = (long)(m0 + r) * Cdim + c;
            float base = accumulate ? out[idx] : biasvec[c];
            out[idx] = base + sv[r];
        }
    }
}

// ---------------- 7. decay = exp(-exp(w)); k *= (1-decay) ----------------
__global__ void decayk_kernel() {
    long i = (long)blockIdx.x * 256 + threadIdx.x;
    float d = expf(-expf(g_w[i]));
    g_w[i] = d;
    g_k[i] *= (1.0f - d);
}

// ---------------- 8. WKV scan ----------------
__global__ __launch_bounds__(64) void wkv_scan_kernel(const float* __restrict__ state0,
                                                      float* __restrict__ stateout) {
    int bn = blockIdx.x;          // 0..63
    int b = bn >> 5;
    int n = bn & 31;
    int j = threadIdx.x;

    float st[64];
    #pragma unroll
    for (int i = 0; i < 64; i++) st[i] = state0[((long)bn * 64 + i) * 64 + j];

    __shared__ float sr[64], sk[64], sd[64];

    long base = ((long)b * Tdim) * Cdim + n * 64;
    float nr = g_r[base + j], nk = g_k[base + j], nd = g_w[base + j];
    float nv = g_v[base + j], nv2 = g_v2[base + j];

    for (int t = 0; t < Tdim; t++) {
        long nb = (t == Tdim - 1) ? base : base + Cdim;
        float cr = nr, ck = nk, cd = nd, cv = nv, cv2 = nv2;
        nr = g_r[nb + j]; nk = g_k[nb + j]; nd = g_w[nb + j];
        nv = g_v[nb + j]; nv2 = g_v2[nb + j];

        sr[j] = cr; sk[j] = ck; sd[j] = cd;
        __syncthreads();

        float y0 = 0.f, y1 = 0.f, y2 = 0.f, y3 = 0.f;
        #pragma unroll
        for (int i = 0; i < 64; i += 4) {
            y0 += sr[i]     * st[i];
            y1 += sr[i + 1] * st[i + 1];
            y2 += sr[i + 2] * st[i + 2];
            y3 += sr[i + 3] * st[i + 3];
        }
        g_y[base + j] = ((y0 + y1) + (y2 + y3)) + cv2;

        #pragma unroll
        for (int i = 0; i < 64; i++) st[i] = st[i] * sd[i] + sk[i] * cv;
        __syncthreads();
        base = nb;
    }
    #pragma unroll
    for (int i = 0; i < 64; i++) stateout[((long)bn * 64 + i) * 64 + j] = st[i];
}

// ---------------- 9. layernorm on y -> g_xmix ----------------
__global__ __launch_bounds__(256) void ln_kernel(const float* __restrict__ g,
                                                 const float* __restrict__ bb) {
    __shared__ float red[256];
    int m = blockIdx.x, tid = threadIdx.x;
    const float* row = g_y + (long)m * Cdim;
    float s1 = 0.f, s2 = 0.f;
    for (int c = tid; c < Cdim; c += 256) {
        float v = row[c];
        s1 += v;
        s2 += v * v;
    }
    red[tid] = s1;
    __syncthreads();
    for (int s = 128; s > 0; s >>= 1) {
        if (tid < s) red[tid] += red[tid + s];
        __syncthreads();
    }
    float mu = red[0] * (1.0f / Cdim);
    __syncthreads();
    red[tid] = s2;
    __syncthreads();
    for (int s = 128; s > 0; s >>= 1) {
        if (tid < s) red[tid] += red[tid + s];
        __syncthreads();
    }
    float var = red[0] * (1.0f / Cdim) - mu * mu;
    float rs = rsqrtf(var + 1e-5f);
    for (int c = tid; c < Cdim; c += 256)
        g_xmix[(long)m * Cdim + c] = (row[c] - mu) * rs * g[c] + bb[c];
}

// ---------------- 10. tail: x[:, -1] ----------------
__global__ void tail_kernel(const float* __restrict__ x, float* __restrict__ out2) {
    int i = blockIdx.x * 256 + threadIdx.x;
    if (i < Bdim * Cdim) {
        int b = i / Cdim, c = i % Cdim;
        out2[i] = x[((long)b * Tdim + (Tdim - 1)) * Cdim + c];
    }
}

// ---------------- host ----------------
static float* sym(const void* symbol) {
    void* p = nullptr;
    cudaGetSymbolAddress(&p, symbol);
    return (float*)p;
}

extern "C" void kernel_launch(void* const* d_in, const int* in_sizes, int n_in,
                              void* d_out, int out_size) {
    const float* x       = (const float*)d_in[0];
    const float* wkv0    = (const float*)d_in[1];
    const float* shift   = (const float*)d_in[2];
    const float* maa_x   = (const float*)d_in[3];
    const float* maa_r   = (const float*)d_in[4];
    const float* maa_k   = (const float*)d_in[5];
    const float* maa_v   = (const float*)d_in[6];
    const float* maa_w   = (const float*)d_in[7];
    const float* maa_v2  = (const float*)d_in[8];
    const float* maa_w1  = (const float*)d_in[9];
    const float* maa_w2  = (const float*)d_in[10];
    const float* tdecay  = (const float*)d_in[11];
    const float* dec_w1  = (const float*)d_in[12];
    const float* dec_w2  = (const float*)d_in[13];
    const float* v2_w1   = (const float*)d_in[14];
    const float* v2_w2   = (const float*)d_in[15];
    const float* Wr      = (const float*)d_in[16];
    const float* Wk      = (const float*)d_in[17];
    const float* Wv      = (const float*)d_in[18];
    const float* Wo      = (const float*)d_in[19];
    const float* ln_g    = (const float*)d_in[20];
    const float* ln_b    = (const float*)d_in[21];
    float* out = (float*)d_out;

    float* p_xr  = sym(g_xr);
    float* p_xk  = sym(g_xk);
    float* p_xv  = sym(g_xv);
    float* p_xw  = sym(g_xw);
    float* p_xv2 = sym(g_xv2);
    float* p_r   = sym(g_r);
    float* p_k   = sym(g_k);
    float* p_v   = sym(g_v);
    float* p_v2  = sym(g_v2);
    float* p_w   = sym(g_w);
    float* p_xm  = sym(g_xmix);

    dim3 tgrid(Cdim / TBN, BT / TBM);  // (16, 64)

    prep_kernel<<<BTC / 256, 256>>>(x, shift, maa_x);
    xxx_kernel<<<BT / 4, 256>>>(maa_w1);
    mixout_kernel<<<BT / 4, 256>>>(x, maa_r, maa_k, maa_v, maa_w, maa_v2, maa_w2);

    tgemm_nt<<<tgrid, 256>>>(p_xr,  Wr, p_r,  BT, Cdim, Cdim);
    tgemm_nt<<<tgrid, 256>>>(p_xk,  Wk, p_k,  BT, Cdim, Cdim);
    tgemm_nt<<<tgrid, 256>>>(p_xv,  Wv, p_v,  BT, Cdim, Cdim);
    tgemm_nt<<<tgrid, 256>>>(p_xv2, Wv, p_v2, BT, Cdim, Cdim);

    lora1_kernel<<<BT / 4, 256>>>(p_xv2, v2_w1);
    lora2_kernel<<<BT / 4, 256>>>(v2_w2, p_v2, nullptr, 1);
    lora1_kernel<<<BT / 4, 256>>>(p_xw, dec_w1);
    lora2_kernel<<<BT / 4, 256>>>(dec_w2, p_w, tdecay, 0);

    decayk_kernel<<<BTC / 256, 256>>>();

    wkv_scan_kernel<<<Bdim * Nheads, 64>>>(wkv0, out + BTC);

    ln_kernel<<<BT, 256>>>(ln_g, ln_b);
    tgemm_nt<<<tgrid, 256>>>(p_xm, Wo, out, BT, Cdim, Cdim);

    tail_kernel<<<16, 256>>>(x, out + BTC + BNHH);
}

// round 4
// speedup vs baseline: 1.8943x; 1.2920x over previous
#include <cuda_runtime.h>
#include <math.h>
#include <stdint.h>

#define Bdim 2
#define Tdim 4096
#define Cdim 2048
#define Hdim 64
#define Nheads 32
#define BT   (Bdim*Tdim)            // 8192
#define BTC  (Bdim*Tdim*Cdim)       // 16777216
#define BNHH (Bdim*Nheads*Hdim*Hdim) // 262144
#define CC   (Cdim*Cdim)            // 4194304

// ---------------- scratch ----------------
__device__ float g_dxprev[BTC];
__device__ float g_xmix[BTC];
__device__ float g_xr[BTC];
__device__ float g_xk[BTC];
__device__ float g_xv[BTC];
__device__ float g_xw[BTC];
__device__ float g_xv2[BTC];
__device__ float g_r[BTC];
__device__ float g_k[BTC];
__device__ float g_v[BTC];
__device__ float g_v2[BTC];
__device__ float g_w[BTC];
__device__ float g_y[BTC];
__device__ float g_xxx[BT*160];
__device__ float g_h[BT*64];
// tf32-rounded weight copies
__device__ float g_wr[CC];
__device__ float g_wk[CC];
__device__ float g_wv[CC];
__device__ float g_wo[CC];

// ---------------- helpers ----------------
__device__ __forceinline__ float f2tf32(float x) {
    uint32_t u;
    asm("cvt.rna.tf32.f32 %0, %1;" : "=r"(u) : "f"(x));
    return __uint_as_float(u);
}
__device__ __forceinline__ uint32_t smem_u32(const void* p) {
    uint32_t a;
    asm("{ .reg .u64 t; cvta.to.shared.u64 t, %1; cvt.u32.u64 %0, t; }" : "=r"(a) : "l"(p));
    return a;
}
__device__ __forceinline__ void cp16(uint32_t dst, const void* src) {
    asm volatile("cp.async.cg.shared.global [%0], [%1], 16;" :: "r"(dst), "l"(src));
}
__device__ __forceinline__ void mma_tf32(float* c, const uint32_t* a, const uint32_t* b) {
    asm volatile("mma.sync.aligned.m16n8k8.row.col.f32.tf32.tf32.f32 "
        "{%0,%1,%2,%3}, {%4,%5,%6,%7}, {%8,%9}, {%0,%1,%2,%3};"
        : "+f"(c[0]), "+f"(c[1]), "+f"(c[2]), "+f"(c[3])
        : "r"(a[0]), "r"(a[1]), "r"(a[2]), "r"(a[3]), "r"(b[0]), "r"(b[1]));
}

// ---------------- 0. tf32 rounding of weights ----------------
__global__ void cvtw_kernel(const float* __restrict__ src, float* __restrict__ dst) {
    long i = ((long)blockIdx.x * 256 + threadIdx.x) * 4;
    float4 v = *(const float4*)(src + i);
    v.x = f2tf32(v.x); v.y = f2tf32(v.y); v.z = f2tf32(v.z); v.w = f2tf32(v.w);
    *(float4*)(dst + i) = v;
}

// ---------------- 1. token shift + base mix ----------------
__global__ void prep_kernel(const float* __restrict__ x,
                            const float* __restrict__ shift,
                            const float* __restrict__ maa_x) {
    long idx = (long)blockIdx.x * 256 + threadIdx.x;
    int c = (int)(idx & (Cdim - 1));
    long tc = idx % ((long)Tdim * Cdim);
    float prev;
    if (tc < Cdim) {
        long b = idx / ((long)Tdim * Cdim);
        prev = shift[b * Cdim + c];
    } else {
        prev = x[idx - Cdim];
    }
    float xc = x[idx];
    float dx = prev - xc;
    g_dxprev[idx] = dx;
    g_xmix[idx] = xc + dx * maa_x[c];
}

// ---------------- 2. xxx = tanh(xmix @ maa_w1), 8 rows/block ----------------
__global__ __launch_bounds__(160) void xxx_kernel(const float* __restrict__ w1) {
    __shared__ float sx[8][256];
    int m0 = blockIdx.x * 8;
    int tid = threadIdx.x;  // 0..159 = output col j
    float acc[8];
    #pragma unroll
    for (int r = 0; r < 8; r++) acc[r] = 0.f;
    for (int kb = 0; kb < Cdim; kb += 256) {
        __syncthreads();
        for (int i = tid; i < 8 * 256; i += 160)
            sx[i >> 8][i & 255] = g_xmix[(long)(m0 + (i >> 8)) * Cdim + kb + (i & 255)];
        __syncthreads();
        for (int k = 0; k < 256; k++) {
            float w = w1[(kb + k) * 160 + tid];
            #pragma unroll
            for (int r = 0; r < 8; r++) acc[r] += sx[r][k] * w;
        }
    }
    #pragma unroll
    for (int r = 0; r < 8; r++) g_xxx[(m0 + r) * 160 + tid] = tanhf(acc[r]);
}

// ---------------- 3. mix coefficients, 8 rows/block (writes tf32-rounded GEMM inputs) ----------------
__global__ __launch_bounds__(256) void mixout_kernel(
    const float* __restrict__ x,
    const float* __restrict__ maa_r, const float* __restrict__ maa_k,
    const float* __restrict__ maa_v, const float* __restrict__ maa_w,
    const float* __restrict__ maa_v2, const float* __restrict__ w2) {
    __shared__ float sx[8][160];
    int m0 = blockIdx.x * 8;
    int tid = threadIdx.x;
    for (int i = tid; i < 8 * 160; i += 256)
        sx[i / 160][i % 160] = g_xxx[(m0 + i / 160) * 160 + (i % 160)];
    __syncthreads();
    for (int c = tid; c < Cdim; c += 256) {
        float mr = maa_r[c], mk = maa_k[c], mv = maa_v[c], mw = maa_w[c], mv2 = maa_v2[c];
        float acc[8][5];
        #pragma unroll
        for (int r = 0; r < 8; r++)
            #pragma unroll
            for (int f = 0; f < 5; f++) acc[r][f] = 0.f;
        #pragma unroll
        for (int f = 0; f < 5; f++) {
            #pragma unroll 8
            for (int l = 0; l < 32; l++) {
                float wv = w2[(f * 32 + l) * Cdim + c];
                #pragma unroll
                for (int r = 0; r < 8; r++) acc[r][f] += sx[r][f * 32 + l] * wv;
            }
        }
        #pragma unroll
        for (int r = 0; r < 8; r++) {
            long idx = (long)(m0 + r) * Cdim + c;
            float xc = x[idx];
            float dx = g_dxprev[idx];
            g_xr[idx]  = f2tf32(xc + dx * (mr  + acc[r][0]));
            g_xk[idx]  = f2tf32(xc + dx * (mk  + acc[r][1]));
            g_xv[idx]  = f2tf32(xc + dx * (mv  + acc[r][2]));
            g_xw[idx]  = xc + dx * (mw  + acc[r][3]);
            g_xv2[idx] = f2tf32(xc + dx * (mv2 + acc[r][4]));
        }
    }
}

// ---------------- 4. TF32 mma.sync GEMM, cp.async 4-stage ----------------
// C[m][n] = sum_k A[m][k]*B[n][k]; A,B already tf32-rounded
#define GM 256
#define GN 128
#define GK 16
#define GST 20                   // smem row stride in floats (80B, 16B aligned)
#define A_ST (GM*GST)            // 5120 floats
#define B_ST (GN*GST)            // 2560 floats
#define ST_FLOATS (A_ST+B_ST)    // 7680
#define GSMEM (ST_FLOATS*4*4)    // 122880 bytes

__global__ __launch_bounds__(256, 1) void tf32_gemm(const float* __restrict__ A,
                                                    const float* __restrict__ B,
                                                    float* __restrict__ C,
                                                    int M, int N, int K) {
    extern __shared__ float smf[];
    uint32_t sb = smem_u32(smf);
    int tid = threadIdx.x;
    int wid = tid >> 5, lane = tid & 31;
    int g = lane >> 2, tg = lane & 3;
    long bm = blockIdx.y * GM, bn = blockIdx.x * GN;
    int wm = (wid & 3) * 64, wn = (wid >> 2) * 64;

    int row_ld = tid >> 2;          // 0..63
    int kc = (tid & 3) * 4;         // 0,4,8,12

    float acc[4][8][4];
    #pragma unroll
    for (int i = 0; i < 4; i++)
        #pragma unroll
        for (int j = 0; j < 8; j++)
            #pragma unroll
            for (int q = 0; q < 4; q++) acc[i][j][q] = 0.f;

    const int kt = K / GK;  // 128

    #define ISSUE(s)                                                              \
        do {                                                                      \
            int _buf = (s) & 3;                                                   \
            long _k0 = (long)(s) * GK + kc;                                       \
            const float* _ga = A + (bm + row_ld) * K + _k0;                       \
            uint32_t _da = sb + (_buf * ST_FLOATS + row_ld * GST + kc) * 4;       \
            _Pragma("unroll")                                                     \
            for (int _i = 0; _i < 4; _i++)                                        \
                cp16(_da + _i * 64 * GST * 4, _ga + (long)_i * 64 * K);           \
            const float* _gb = B + (bn + row_ld) * K + _k0;                       \
            uint32_t _db = sb + (_buf * ST_FLOATS + A_ST + row_ld * GST + kc) * 4;\
            _Pragma("unroll")                                                     \
            for (int _i = 0; _i < 2; _i++)                                        \
                cp16(_db + _i * 64 * GST * 4, _gb + (long)_i * 64 * K);           \
        } while (0)

    ISSUE(0); asm volatile("cp.async.commit_group;");
    ISSUE(1); asm volatile("cp.async.commit_group;");
    ISSUE(2); asm volatile("cp.async.commit_group;");

    for (int s = 0; s < kt; s++) {
        asm volatile("cp.async.wait_group 2;");
        __syncthreads();
        const float* As = smf + (s & 3) * ST_FLOATS;
        const float* Bs = As + A_ST;
        #pragma unroll
        for (int kk = 0; kk < GK; kk += 8) {
            uint32_t af[4][4], bf[8][2];
            #pragma unroll
            for (int i = 0; i < 4; i++) {
                int r0 = wm + i * 16 + g;
                af[i][0] = __float_as_uint(As[r0 * GST + kk + tg]);
                af[i][1] = __float_as_uint(As[(r0 + 8) * GST + kk + tg]);
                af[i][2] = __float_as_uint(As[r0 * GST + kk + tg + 4]);
                af[i][3] = __float_as_uint(As[(r0 + 8) * GST + kk + tg + 4]);
            }
            #pragma unroll
            for (int j = 0; j < 8; j++) {
                int c0 = wn + j * 8 + g;
                bf[j][0] = __float_as_uint(Bs[c0 * GST + kk + tg]);
                bf[j][1] = __float_as_uint(Bs[c0 * GST + kk + tg + 4]);
            }
            #pragma unroll
            for (int i = 0; i < 4; i++)
                #pragma unroll
                for (int j = 0; j < 8; j++)
                    mma_tf32(acc[i][j], af[i], bf[j]);
        }
        if (s + 3 < kt) ISSUE(s + 3);
        asm volatile("cp.async.commit_group;");
    }
    #undef ISSUE

    #pragma unroll
    for (int i = 0; i < 4; i++) {
        #pragma unroll
        for (int j = 0; j < 8; j++) {
            long row = bm + wm + i * 16 + g;
            long col = bn + wn + j * 8 + tg * 2;
            *(float2*)(C + row * N + col) = make_float2(acc[i][j][0], acc[i][j][1]);
            *(float2*)(C + (row + 8) * N + col) = make_float2(acc[i][j][2], acc[i][j][3]);
        }
    }
}

// ---------------- 5. LoRA stage 1: g_h = tanh(A @ W), 8 rows/block ----------------
__global__ __launch_bounds__(256) void lora1_kernel(const float* __restrict__ A,
                                                    const float* __restrict__ W) {
    __shared__ float sa[8][256];
    int m0 = blockIdx.x * 8;
    int tid = threadIdx.x;
    int j = tid & 63;
    int rg = tid >> 6;  // 0..3 -> rows rg, rg+4
    float a0 = 0.f, a1 = 0.f;
    for (int kb = 0; kb < Cdim; kb += 256) {
        __syncthreads();
        for (int i = tid; i < 8 * 256; i += 256)
            sa[i >> 8][i & 255] = A[(long)(m0 + (i >> 8)) * Cdim + kb + (i & 255)];
        __syncthreads();
        for (int k = 0; k < 256; k++) {
            float w = W[(kb + k) * 64 + j];
            a0 += sa[rg][k] * w;
            a1 += sa[rg + 4][k] * w;
        }
    }
    g_h[(m0 + rg) * 64 + j] = tanhf(a0);
    g_h[(m0 + rg + 4) * 64 + j] = tanhf(a1);
}

// ---------------- 6. LoRA stage 2: out = base + h @ W2, 8 rows/block ----------------
__global__ __launch_bounds__(256) void lora2_kernel(const float* __restrict__ W2,
                                                    float* __restrict__ out,
                                                    const float* __restrict__ biasvec,
                                                    int accumulate) {
    __shared__ float sh[8][64];
    int m0 = blockIdx.x * 8;
    int tid = threadIdx.x;
    for (int i = tid; i < 8 * 64; i += 256)
        sh[i >> 6][i & 63] = g_h[(m0 + (i >> 6)) * 64 + (i & 63)];
    __syncthreads();
    for (int c = tid; c < Cdim; c += 256) {
        float sv[8];
        #pragma unroll
        for (int r = 0; r < 8; r++) sv[r] = 0.f;
        #pragma unroll 8
        for (int l = 0; l < 64; l++) {
            float w = W2[l * Cdim + c];
            #pragma unroll
            for (int r = 0; r < 8; r++) sv[r] += sh[r][l] * w;
        }
        #pragma unroll
        for (int r = 0; r < 8; r++) {
            long idx = (long)(m0 + r) * Cdim + c;
            float base = accumulate ? out[idx] : biasvec[c];
            out[idx] = base + sv[r];
        }
    }
}

// ---------------- 7. decay ----------------
__global__ void decayk_kernel() {
    long i = (long)blockIdx.x * 256 + threadIdx.x;
    float d = expf(-expf(g_w[i]));
    g_w[i] = d;
    g_k[i] *= (1.0f - d);
}

// ---------------- 8. WKV scan ----------------
__global__ __launch_bounds__(64) void wkv_scan_kernel(const float* __restrict__ state0,
                                                      float* __restrict__ stateout) {
    int bn = blockIdx.x;
    int b = bn >> 5;
    int n = bn & 31;
    int j = threadIdx.x;

    float st[64];
    #pragma unroll
    for (int i = 0; i < 64; i++) st[i] = state0[((long)bn * 64 + i) * 64 + j];

    __shared__ float sr[64], sk[64], sd[64];

    long base = ((long)b * Tdim) * Cdim + n * 64;
    float nr = g_r[base + j], nk = g_k[base + j], nd = g_w[base + j];
    float nv = g_v[base + j], nv2 = g_v2[base + j];

    for (int t = 0; t < Tdim; t++) {
        long nb = (t == Tdim - 1) ? base : base + Cdim;
        float cr = nr, ck = nk, cd = nd, cv = nv, cv2 = nv2;
        nr = g_r[nb + j]; nk = g_k[nb + j]; nd = g_w[nb + j];
        nv = g_v[nb + j]; nv2 = g_v2[nb + j];

        sr[j] = cr; sk[j] = ck; sd[j] = cd;
        __syncthreads();

        float y0 = 0.f, y1 = 0.f, y2 = 0.f, y3 = 0.f;
        #pragma unroll
        for (int i = 0; i < 64; i += 4) {
            y0 += sr[i]     * st[i];
            y1 += sr[i + 1] * st[i + 1];
            y2 += sr[i + 2] * st[i + 2];
            y3 += sr[i + 3] * st[i + 3];
        }
        g_y[base + j] = ((y0 + y1) + (y2 + y3)) + cv2;

        #pragma unroll
        for (int i = 0; i < 64; i++) st[i] = st[i] * sd[i] + sk[i] * cv;
        __syncthreads();
        base = nb;
    }
    #pragma unroll
    for (int i = 0; i < 64; i++) stateout[((long)bn * 64 + i) * 64 + j] = st[i];
}

// ---------------- 9. layernorm (writes tf32-rounded GEMM input) ----------------
__global__ __launch_bounds__(256) void ln_kernel(const float* __restrict__ g,
                                                 const float* __restrict__ bb) {
    __shared__ float red[256];
    int m = blockIdx.x, tid = threadIdx.x;
    const float* row = g_y + (long)m * Cdim;
    float s1 = 0.f, s2 = 0.f;
    for (int c = tid; c < Cdim; c += 256) {
        float v = row[c];
        s1 += v;
        s2 += v * v;
    }
    red[tid] = s1;
    __syncthreads();
    for (int s = 128; s > 0; s >>= 1) {
        if (tid < s) red[tid] += red[tid + s];
        __syncthreads();
    }
    float mu = red[0] * (1.0f / Cdim);
    __syncthreads();
    red[tid] = s2;
    __syncthreads();
    for (int s = 128; s > 0; s >>= 1) {
        if (tid < s) red[tid] += red[tid + s];
        __syncthreads();
    }
    float var = red[0] * (1.0f / Cdim) - mu * mu;
    float rs = rsqrtf(var + 1e-5f);
    for (int c = tid; c < Cdim; c += 256)
        g_xmix[(long)m * Cdim + c] = f2tf32((row[c] - mu) * rs * g[c] + bb[c]);
}

// ---------------- 10. tail ----------------
__global__ void tail_kernel(const float* __restrict__ x, float* __restrict__ out2) {
    int i = blockIdx.x * 256 + threadIdx.x;
    if (i < Bdim * Cdim) {
        int b = i / Cdim, c = i % Cdim;
        out2[i] = x[((long)b * Tdim + (Tdim - 1)) * Cdim + c];
    }
}

// ---------------- host ----------------
static float* sym(const void* symbol) {
    void* p = nullptr;
    cudaGetSymbolAddress(&p, symbol);
    return (float*)p;
}

extern "C" void kernel_launch(void* const* d_in, const int* in_sizes, int n_in,
                              void* d_out, int out_size) {
    const float* x       = (const float*)d_in[0];
    const float* wkv0    = (const float*)d_in[1];
    const float* shift   = (const float*)d_in[2];
    const float* maa_x   = (const float*)d_in[3];
    const float* maa_r   = (const float*)d_in[4];
    const float* maa_k   = (const float*)d_in[5];
    const float* maa_v   = (const float*)d_in[6];
    const float* maa_w   = (const float*)d_in[7];
    const float* maa_v2  = (const float*)d_in[8];
    const float* maa_w1  = (const float*)d_in[9];
    const float* maa_w2  = (const float*)d_in[10];
    const float* tdecay  = (const float*)d_in[11];
    const float* dec_w1  = (const float*)d_in[12];
    const float* dec_w2  = (const float*)d_in[13];
    const float* v2_w1   = (const float*)d_in[14];
    const float* v2_w2   = (const float*)d_in[15];
    const float* Wr      = (const float*)d_in[16];
    const float* Wk      = (const float*)d_in[17];
    const float* Wv      = (const float*)d_in[18];
    const float* Wo      = (const float*)d_in[19];
    const float* ln_g    = (const float*)d_in[20];
    const float* ln_b    = (const float*)d_in[21];
    float* out = (float*)d_out;

    float* p_xr  = sym(g_xr);
    float* p_xk  = sym(g_xk);
    float* p_xv  = sym(g_xv);
    float* p_xw  = sym(g_xw);
    float* p_xv2 = sym(g_xv2);
    float* p_v2  = sym(g_v2);
    float* p_r   = sym(g_r);
    float* p_k   = sym(g_k);
    float* p_v   = sym(g_v);
    float* p_w   = sym(g_w);
    float* p_xm  = sym(g_xmix);
    float* p_wr  = sym(g_wr);
    float* p_wk  = sym(g_wk);
    float* p_wv  = sym(g_wv);
    float* p_wo  = sym(g_wo);

    static int attr_set = 0;
    if (!attr_set) {
        cudaFuncSetAttribute(tf32_gemm, cudaFuncAttributeMaxDynamicSharedMemorySize, GSMEM);
        attr_set = 1;
    }

    dim3 ggrid(Cdim / GN, BT / GM);  // (16, 32)

    // weight tf32 conversion (independent; run first)
    cvtw_kernel<<<CC / 1024, 256>>>(Wr, p_wr);
    cvtw_kernel<<<CC / 1024, 256>>>(Wk, p_wk);
    cvtw_kernel<<<CC / 1024, 256>>>(Wv, p_wv);
    cvtw_kernel<<<CC / 1024, 256>>>(Wo, p_wo);

    prep_kernel<<<BTC / 256, 256>>>(x, shift, maa_x);
    xxx_kernel<<<BT / 8, 160>>>(maa_w1);
    mixout_kernel<<<BT / 8, 256>>>(x, maa_r, maa_k, maa_v, maa_w, maa_v2, maa_w2);

    tf32_gemm<<<ggrid, 256, GSMEM>>>(p_xr,  p_wr, p_r,  BT, Cdim, Cdim);
    tf32_gemm<<<ggrid, 256, GSMEM>>>(p_xk,  p_wk, p_k,  BT, Cdim, Cdim);
    tf32_gemm<<<ggrid, 256, GSMEM>>>(p_xv,  p_wv, p_v,  BT, Cdim, Cdim);
    tf32_gemm<<<ggrid, 256, GSMEM>>>(p_xv2, p_wv, p_v2, BT, Cdim, Cdim);

    lora1_kernel<<<BT / 8, 256>>>(p_xv2, v2_w1);
    lora2_kernel<<<BT / 8, 256>>>(v2_w2, p_v2, nullptr, 1);
    lora1_kernel<<<BT / 8, 256>>>(p_xw, dec_w1);
    lora2_kernel<<<BT / 8, 256>>>(dec_w2, p_w, tdecay, 0);

    decayk_kernel<<<BTC / 256, 256>>>();

    wkv_scan_kernel<<<Bdim * Nheads, 64>>>(wkv0, out + BTC);

    ln_kernel<<<BT, 256>>>(ln_g, ln_b);
    tf32_gemm<<<ggrid, 256, GSMEM>>>(p_xm, p_wo, out, BT, Cdim, Cdim);

    tail_kernel<<<16, 256>>>(x, out + BTC + BNHH);
}

// round 5
// speedup vs baseline: 2.4716x; 1.3047x over previous
#include <cuda_runtime.h>
#include <math.h>
#include <stdint.h>

#define Bdim 2
#define Tdim 4096
#define Cdim 2048
#define Hdim 64
#define Nheads 32
#define BT   (Bdim*Tdim)            // 8192
#define BTC  (Bdim*Tdim*Cdim)       // 16777216
#define BNHH (Bdim*Nheads*Hdim*Hdim) // 262144
#define CC   (Cdim*Cdim)            // 4194304
#define NCHUNK 64                   // chunks along T
#define CLEN  64                    // chunk length (Tdim/NCHUNK)
#define NHEADS_TOT 64               // Bdim*Nheads

// ---------------- scratch ----------------
__device__ float g_dxprev[BTC];
__device__ float g_xmix[BTC];
__device__ float g_xr[BTC];
__device__ float g_xk[BTC];
__device__ float g_xv[BTC];
__device__ float g_xw[BTC];
__device__ float g_xv2[BTC];
__device__ float g_r[BTC];
__device__ float g_k[BTC];
__device__ float g_v[BTC];
__device__ float g_v2[BTC];
__device__ float g_w[BTC];
__device__ float g_y[BTC];
__device__ float g_xxx[BT*160];
__device__ float g_h[BT*64];
// tf32-rounded weight copies
__device__ float g_wr[CC];
__device__ float g_wk[CC];
__device__ float g_wv[CC];
__device__ float g_wo[CC];
// chunked-scan buffers
__device__ float g_S[NCHUNK*NHEADS_TOT*Hdim*Hdim];    // per-chunk contribution
__device__ float g_bst[NCHUNK*NHEADS_TOT*Hdim*Hdim];  // per-chunk start state
__device__ float g_P[NCHUNK*NHEADS_TOT*Hdim];         // per-chunk row decay product

// ---------------- helpers ----------------
__device__ __forceinline__ float f2tf32(float x) {
    uint32_t u;
    asm("cvt.rna.tf32.f32 %0, %1;" : "=r"(u) : "f"(x));
    return __uint_as_float(u);
}
__device__ __forceinline__ uint32_t smem_u32(const void* p) {
    uint32_t a;
    asm("{ .reg .u64 t; cvta.to.shared.u64 t, %1; cvt.u32.u64 %0, t; }" : "=r"(a) : "l"(p));
    return a;
}
__device__ __forceinline__ void cp16(uint32_t dst, const void* src) {
    asm volatile("cp.async.cg.shared.global [%0], [%1], 16;" :: "r"(dst), "l"(src));
}
__device__ __forceinline__ void mma_tf32(float* c, const uint32_t* a, const uint32_t* b) {
    asm volatile("mma.sync.aligned.m16n8k8.row.col.f32.tf32.tf32.f32 "
        "{%0,%1,%2,%3}, {%4,%5,%6,%7}, {%8,%9}, {%0,%1,%2,%3};"
        : "+f"(c[0]), "+f"(c[1]), "+f"(c[2]), "+f"(c[3])
        : "r"(a[0]), "r"(a[1]), "r"(a[2]), "r"(a[3]), "r"(b[0]), "r"(b[1]));
}

// ---------------- 0. tf32 rounding of weights ----------------
__global__ void cvtw_kernel(const float* __restrict__ src, float* __restrict__ dst) {
    long i = ((long)blockIdx.x * 256 + threadIdx.x) * 4;
    float4 v = *(const float4*)(src + i);
    v.x = f2tf32(v.x); v.y = f2tf32(v.y); v.z = f2tf32(v.z); v.w = f2tf32(v.w);
    *(float4*)(dst + i) = v;
}

// ---------------- 1. token shift + base mix ----------------
__global__ void prep_kernel(const float* __restrict__ x,
                            const float* __restrict__ shift,
                            const float* __restrict__ maa_x) {
    long idx = (long)blockIdx.x * 256 + threadIdx.x;
    int c = (int)(idx & (Cdim - 1));
    long tc = idx % ((long)Tdim * Cdim);
    float prev;
    if (tc < Cdim) {
        long b = idx / ((long)Tdim * Cdim);
        prev = shift[b * Cdim + c];
    } else {
        prev = x[idx - Cdim];
    }
    float xc = x[idx];
    float dx = prev - xc;
    g_dxprev[idx] = dx;
    g_xmix[idx] = xc + dx * maa_x[c];
}

// ---------------- 2. xxx = tanh(xmix @ maa_w1), 8 rows/block ----------------
__global__ __launch_bounds__(160) void xxx_kernel(const float* __restrict__ w1) {
    __shared__ float sx[8][256];
    int m0 = blockIdx.x * 8;
    int tid = threadIdx.x;
    float acc[8];
    #pragma unroll
    for (int r = 0; r < 8; r++) acc[r] = 0.f;
    for (int kb = 0; kb < Cdim; kb += 256) {
        __syncthreads();
        for (int i = tid; i < 8 * 256; i += 160)
            sx[i >> 8][i & 255] = g_xmix[(long)(m0 + (i >> 8)) * Cdim + kb + (i & 255)];
        __syncthreads();
        for (int k = 0; k < 256; k++) {
            float w = w1[(kb + k) * 160 + tid];
            #pragma unroll
            for (int r = 0; r < 8; r++) acc[r] += sx[r][k] * w;
        }
    }
    #pragma unroll
    for (int r = 0; r < 8; r++) g_xxx[(m0 + r) * 160 + tid] = tanhf(acc[r]);
}

// ---------------- 3. mix coefficients, 8 rows/block ----------------
__global__ __launch_bounds__(256) void mixout_kernel(
    const float* __restrict__ x,
    const float* __restrict__ maa_r, const float* __restrict__ maa_k,
    const float* __restrict__ maa_v, const float* __restrict__ maa_w,
    const float* __restrict__ maa_v2, const float* __restrict__ w2) {
    __shared__ float sx[8][160];
    int m0 = blockIdx.x * 8;
    int tid = threadIdx.x;
    for (int i = tid; i < 8 * 160; i += 256)
        sx[i / 160][i % 160] = g_xxx[(m0 + i / 160) * 160 + (i % 160)];
    __syncthreads();
    for (int c = tid; c < Cdim; c += 256) {
        float mr = maa_r[c], mk = maa_k[c], mv = maa_v[c], mw = maa_w[c], mv2 = maa_v2[c];
        float acc[8][5];
        #pragma unroll
        for (int r = 0; r < 8; r++)
            #pragma unroll
            for (int f = 0; f < 5; f++) acc[r][f] = 0.f;
        #pragma unroll
        for (int f = 0; f < 5; f++) {
            #pragma unroll 8
            for (int l = 0; l < 32; l++) {
                float wv = w2[(f * 32 + l) * Cdim + c];
                #pragma unroll
                for (int r = 0; r < 8; r++) acc[r][f] += sx[r][f * 32 + l] * wv;
            }
        }
        #pragma unroll
        for (int r = 0; r < 8; r++) {
            long idx = (long)(m0 + r) * Cdim + c;
            float xc = x[idx];
            float dx = g_dxprev[idx];
            g_xr[idx]  = f2tf32(xc + dx * (mr  + acc[r][0]));
            g_xk[idx]  = f2tf32(xc + dx * (mk  + acc[r][1]));
            g_xv[idx]  = f2tf32(xc + dx * (mv  + acc[r][2]));
            g_xw[idx]  = xc + dx * (mw  + acc[r][3]);
            g_xv2[idx] = f2tf32(xc + dx * (mv2 + acc[r][4]));
        }
    }
}

// ---------------- 4. TF32 mma.sync GEMM, cp.async 4-stage ----------------
#define GM 256
#define GN 128
#define GK 16
#define GST 20
#define A_ST (GM*GST)
#define B_ST (GN*GST)
#define ST_FLOATS (A_ST+B_ST)
#define GSMEM (ST_FLOATS*4*4)

__global__ __launch_bounds__(256, 1) void tf32_gemm(const float* __restrict__ A,
                                                    const float* __restrict__ B,
                                                    float* __restrict__ C,
                                                    int M, int N, int K) {
    extern __shared__ float smf[];
    uint32_t sb = smem_u32(smf);
    int tid = threadIdx.x;
    int wid = tid >> 5, lane = tid & 31;
    int g = lane >> 2, tg = lane & 3;
    long bm = blockIdx.y * GM, bn = blockIdx.x * GN;
    int wm = (wid & 3) * 64, wn = (wid >> 2) * 64;

    int row_ld = tid >> 2;
    int kc = (tid & 3) * 4;

    float acc[4][8][4];
    #pragma unroll
    for (int i = 0; i < 4; i++)
        #pragma unroll
        for (int j = 0; j < 8; j++)
            #pragma unroll
            for (int q = 0; q < 4; q++) acc[i][j][q] = 0.f;

    const int kt = K / GK;

    #define ISSUE(s)                                                              \
        do {                                                                      \
            int _buf = (s) & 3;                                                   \
            long _k0 = (long)(s) * GK + kc;                                       \
            const float* _ga = A + (bm + row_ld) * K + _k0;                       \
            uint32_t _da = sb + (_buf * ST_FLOATS + row_ld * GST + kc) * 4;       \
            _Pragma("unroll")                                                     \
            for (int _i = 0; _i < 4; _i++)                                        \
                cp16(_da + _i * 64 * GST * 4, _ga + (long)_i * 64 * K);           \
            const float* _gb = B + (bn + row_ld) * K + _k0;                       \
            uint32_t _db = sb + (_buf * ST_FLOATS + A_ST + row_ld * GST + kc) * 4;\
            _Pragma("unroll")                                                     \
            for (int _i = 0; _i < 2; _i++)                                        \
                cp16(_db + _i * 64 * GST * 4, _gb + (long)_i * 64 * K);           \
        } while (0)

    ISSUE(0); asm volatile("cp.async.commit_group;");
    ISSUE(1); asm volatile("cp.async.commit_group;");
    ISSUE(2); asm volatile("cp.async.commit_group;");

    for (int s = 0; s < kt; s++) {
        asm volatile("cp.async.wait_group 2;");
        __syncthreads();
        const float* As = smf + (s & 3) * ST_FLOATS;
        const float* Bs = As + A_ST;
        #pragma unroll
        for (int kk = 0; kk < GK; kk += 8) {
            uint32_t af[4][4], bf[8][2];
            #pragma unroll
            for (int i = 0; i < 4; i++) {
                int r0 = wm + i * 16 + g;
                af[i][0] = __float_as_uint(As[r0 * GST + kk + tg]);
                af[i][1] = __float_as_uint(As[(r0 + 8) * GST + kk + tg]);
                af[i][2] = __float_as_uint(As[r0 * GST + kk + tg + 4]);
                af[i][3] = __float_as_uint(As[(r0 + 8) * GST + kk + tg + 4]);
            }
            #pragma unroll
            for (int j = 0; j < 8; j++) {
                int c0 = wn + j * 8 + g;
                bf[j][0] = __float_as_uint(Bs[c0 * GST + kk + tg]);
                bf[j][1] = __float_as_uint(Bs[c0 * GST + kk + tg + 4]);
            }
            #pragma unroll
            for (int i = 0; i < 4; i++)
                #pragma unroll
                for (int j = 0; j < 8; j++)
                    mma_tf32(acc[i][j], af[i], bf[j]);
        }
        if (s + 3 < kt) ISSUE(s + 3);
        asm volatile("cp.async.commit_group;");
    }
    #undef ISSUE

    #pragma unroll
    for (int i = 0; i < 4; i++) {
        #pragma unroll
        for (int j = 0; j < 8; j++) {
            long row = bm + wm + i * 16 + g;
            long col = bn + wn + j * 8 + tg * 2;
            *(float2*)(C + row * N + col) = make_float2(acc[i][j][0], acc[i][j][1]);
            *(float2*)(C + (row + 8) * N + col) = make_float2(acc[i][j][2], acc[i][j][3]);
        }
    }
}

// ---------------- 5. LoRA stage 1 ----------------
__global__ __launch_bounds__(256) void lora1_kernel(const float* __restrict__ A,
                                                    const float* __restrict__ W) {
    __shared__ float sa[8][256];
    int m0 = blockIdx.x * 8;
    int tid = threadIdx.x;
    int j = tid & 63;
    int rg = tid >> 6;
    float a0 = 0.f, a1 = 0.f;
    for (int kb = 0; kb < Cdim; kb += 256) {
        __syncthreads();
        for (int i = tid; i < 8 * 256; i += 256)
            sa[i >> 8][i & 255] = A[(long)(m0 + (i >> 8)) * Cdim + kb + (i & 255)];
        __syncthreads();
        for (int k = 0; k < 256; k++) {
            float w = W[(kb + k) * 64 + j];
            a0 += sa[rg][k] * w;
            a1 += sa[rg + 4][k] * w;
        }
    }
    g_h[(m0 + rg) * 64 + j] = tanhf(a0);
    g_h[(m0 + rg + 4) * 64 + j] = tanhf(a1);
}

// ---------------- 6. LoRA stage 2 ----------------
__global__ __launch_bounds__(256) void lora2_kernel(const float* __restrict__ W2,
                                                    float* __restrict__ out,
                                                    const float* __restrict__ biasvec,
                                                    int accumulate) {
    __shared__ float sh[8][64];
    int m0 = blockIdx.x * 8;
    int tid = threadIdx.x;
    for (int i = tid; i < 8 * 64; i += 256)
        sh[i >> 6][i & 63] = g_h[(m0 + (i >> 6)) * 64 + (i & 63)];
    __syncthreads();
    for (int c = tid; c < Cdim; c += 256) {
        float sv[8];
        #pragma unroll
        for (int r = 0; r < 8; r++) sv[r] = 0.f;
        #pragma unroll 8
        for (int l = 0; l < 64; l++) {
            float w = W2[l * Cdim + c];
            #pragma unroll
            for (int r = 0; r < 8; r++) sv[r] += sh[r][l] * w;
        }
        #pragma unroll
        for (int r = 0; r < 8; r++) {
            long idx = (long)(m0 + r) * Cdim + c;
            float base = accumulate ? out[idx] : biasvec[c];
            out[idx] = base + sv[r];
        }
    }
}

// ---------------- 8a. WKV phase 1: per-chunk scan from zero state ----------------
// block = (chunk c, head bn); computes S_c and P_c. decay/k-scale fused.
__global__ __launch_bounds__(64) void wkv_phase1() {
    int blk = blockIdx.x;
    int bn = blk & 63;
    int c = blk >> 6;
    int b = bn >> 5, n = bn & 31;
    int j = threadIdx.x;

    float st[64];
    #pragma unroll
    for (int i = 0; i < 64; i++) st[i] = 0.f;
    float pj = 1.f;

    __shared__ float sk[64], sd[64];
    long base = ((long)b * Tdim + (long)c * CLEN) * Cdim + n * 64;

    for (int t = 0; t < CLEN; t++) {
        long idx = base + (long)t * Cdim + j;
        float d = expf(-expf(g_w[idx]));
        float kk = g_k[idx] * (1.0f - d);
        float cv = g_v[idx];
        sk[j] = kk; sd[j] = d;
        __syncthreads();
        #pragma unroll
        for (int i = 0; i < 64; i++) st[i] = st[i] * sd[i] + sk[i] * cv;
        pj *= d;
        __syncthreads();
    }

    long obase = ((long)c * 64 + bn) * 4096;
    #pragma unroll
    for (int i = 0; i < 64; i++) g_S[obase + i * 64 + j] = st[i];
    g_P[((long)c * 64 + bn) * 64 + j] = pj;
}

// ---------------- 8b. WKV phase 2: sequential chunk combine ----------------
// block = head bn; 256 threads, 16 elements each.
__global__ __launch_bounds__(256) void wkv_combine(const float* __restrict__ state0,
                                                   float* __restrict__ stateout) {
    int bn = blockIdx.x;
    int tid = threadIdx.x;
    float stq[16];
    #pragma unroll
    for (int q = 0; q < 16; q++)
        stq[q] = state0[(long)bn * 4096 + tid + 256 * q];

    for (int c = 0; c < NCHUNK; c++) {
        long sbase = ((long)c * 64 + bn) * 4096;
        long pbase = ((long)c * 64 + bn) * 64;
        #pragma unroll
        for (int q = 0; q < 16; q++) {
            int e = tid + 256 * q;
            g_bst[sbase + e] = stq[q];
            stq[q] = g_P[pbase + (e >> 6)] * stq[q] + g_S[sbase + e];
        }
    }
    #pragma unroll
    for (int q = 0; q < 16; q++)
        stateout[(long)bn * 4096 + tid + 256 * q] = stq[q];
}

// ---------------- 8c. WKV phase 3: per-chunk scan from known start state, emits y ----------------
__global__ __launch_bounds__(64) void wkv_phase3() {
    int blk = blockIdx.x;
    int bn = blk & 63;
    int c = blk >> 6;
    int b = bn >> 5, n = bn & 31;
    int j = threadIdx.x;

    float st[64];
    long ibase = ((long)c * 64 + bn) * 4096;
    #pragma unroll
    for (int i = 0; i < 64; i++) st[i] = g_bst[ibase + i * 64 + j];

    __shared__ float sr[64], sk[64], sd[64];
    long base = ((long)b * Tdim + (long)c * CLEN) * Cdim + n * 64;

    for (int t = 0; t < CLEN; t++) {
        long idx = base + (long)t * Cdim + j;
        float rr = g_r[idx];
        float d = expf(-expf(g_w[idx]));
        float kk = g_k[idx] * (1.0f - d);
        float cv = g_v[idx];
        float cv2 = g_v2[idx];
        sr[j] = rr; sk[j] = kk; sd[j] = d;
        __syncthreads();

        float y0 = 0.f, y1 = 0.f, y2 = 0.f, y3 = 0.f;
        #pragma unroll
        for (int i = 0; i < 64; i += 4) {
            y0 += sr[i]     * st[i];
            y1 += sr[i + 1] * st[i + 1];
            y2 += sr[i + 2] * st[i + 2];
            y3 += sr[i + 3] * st[i + 3];
        }
        g_y[idx] = ((y0 + y1) + (y2 + y3)) + cv2;

        #pragma unroll
        for (int i = 0; i < 64; i++) st[i] = st[i] * sd[i] + sk[i] * cv;
        __syncthreads();
    }
}

// ---------------- 9. layernorm ----------------
__global__ __launch_bounds__(256) void ln_kernel(const float* __restrict__ g,
                                                 const float* __restrict__ bb) {
    __shared__ float red[256];
    int m = blockIdx.x, tid = threadIdx.x;
    const float* row = g_y + (long)m * Cdim;
    float s1 = 0.f, s2 = 0.f;
    for (int c = tid; c < Cdim; c += 256) {
        float v = row[c];
        s1 += v;
        s2 += v * v;
    }
    red[tid] = s1;
    __syncthreads();
    for (int s = 128; s > 0; s >>= 1) {
        if (tid < s) red[tid] += red[tid + s];
        __syncthreads();
    }
    float mu = red[0] * (1.0f / Cdim);
    __syncthreads();
    red[tid] = s2;
    __syncthreads();
    for (int s = 128; s > 0; s >>= 1) {
        if (tid < s) red[tid] += red[tid + s];
        __syncthreads();
    }
    float var = red[0] * (1.0f / Cdim) - mu * mu;
    float rs = rsqrtf(var + 1e-5f);
    for (int c = tid; c < Cdim; c += 256)
        g_xmix[(long)m * Cdim + c] = f2tf32((row[c] - mu) * rs * g[c] + bb[c]);
}

// ---------------- 10. tail ----------------
__global__ void tail_kernel(const float* __restrict__ x, float* __restrict__ out2) {
    int i = blockIdx.x * 256 + threadIdx.x;
    if (i < Bdim * Cdim) {
        int b = i / Cdim, c = i % Cdim;
        out2[i] = x[((long)b * Tdim + (Tdim - 1)) * Cdim + c];
    }
}

// ---------------- host ----------------
static float* sym(const void* symbol) {
    void* p = nullptr;
    cudaGetSymbolAddress(&p, symbol);
    return (float*)p;
}

extern "C" void kernel_launch(void* const* d_in, const int* in_sizes, int n_in,
                              void* d_out, int out_size) {
    const float* x       = (const float*)d_in[0];
    const float* wkv0    = (const float*)d_in[1];
    const float* shift   = (const float*)d_in[2];
    const float* maa_x   = (const float*)d_in[3];
    const float* maa_r   = (const float*)d_in[4];
    const float* maa_k   = (const float*)d_in[5];
    const float* maa_v   = (const float*)d_in[6];
    const float* maa_w   = (const float*)d_in[7];
    const float* maa_v2  = (const float*)d_in[8];
    const float* maa_w1  = (const float*)d_in[9];
    const float* maa_w2  = (const float*)d_in[10];
    const float* tdecay  = (const float*)d_in[11];
    const float* dec_w1  = (const float*)d_in[12];
    const float* dec_w2  = (const float*)d_in[13];
    const float* v2_w1   = (const float*)d_in[14];
    const float* v2_w2   = (const float*)d_in[15];
    const float* Wr      = (const float*)d_in[16];
    const float* Wk      = (const float*)d_in[17];
    const float* Wv      = (const float*)d_in[18];
    const float* Wo      = (const float*)d_in[19];
    const float* ln_g    = (const float*)d_in[20];
    const float* ln_b    = (const float*)d_in[21];
    float* out = (float*)d_out;

    float* p_xr  = sym(g_xr);
    float* p_xk  = sym(g_xk);
    float* p_xv  = sym(g_xv);
    float* p_xw  = sym(g_xw);
    float* p_xv2 = sym(g_xv2);
    float* p_v2  = sym(g_v2);
    float* p_r   = sym(g_r);
    float* p_k   = sym(g_k);
    float* p_v   = sym(g_v);
    float* p_w   = sym(g_w);
    float* p_xm  = sym(g_xmix);
    float* p_wr  = sym(g_wr);
    float* p_wk  = sym(g_wk);
    float* p_wv  = sym(g_wv);
    float* p_wo  = sym(g_wo);

    static int attr_set = 0;
    if (!attr_set) {
        cudaFuncSetAttribute(tf32_gemm, cudaFuncAttributeMaxDynamicSharedMemorySize, GSMEM);
        attr_set = 1;
    }

    dim3 ggrid(Cdim / GN, BT / GM);  // (16, 32)

    cvtw_kernel<<<CC / 1024, 256>>>(Wr, p_wr);
    cvtw_kernel<<<CC / 1024, 256>>>(Wk, p_wk);
    cvtw_kernel<<<CC / 1024, 256>>>(Wv, p_wv);
    cvtw_kernel<<<CC / 1024, 256>>>(Wo, p_wo);

    prep_kernel<<<BTC / 256, 256>>>(x, shift, maa_x);
    xxx_kernel<<<BT / 8, 160>>>(maa_w1);
    mixout_kernel<<<BT / 8, 256>>>(x, maa_r, maa_k, maa_v, maa_w, maa_v2, maa_w2);

    tf32_gemm<<<ggrid, 256, GSMEM>>>(p_xr,  p_wr, p_r,  BT, Cdim, Cdim);
    tf32_gemm<<<ggrid, 256, GSMEM>>>(p_xk,  p_wk, p_k,  BT, Cdim, Cdim);
    tf32_gemm<<<ggrid, 256, GSMEM>>>(p_xv,  p_wv, p_v,  BT, Cdim, Cdim);
    tf32_gemm<<<ggrid, 256, GSMEM>>>(p_xv2, p_wv, p_v2, BT, Cdim, Cdim);

    lora1_kernel<<<BT / 8, 256>>>(p_xv2, v2_w1);
    lora2_kernel<<<BT / 8, 256>>>(v2_w2, p_v2, nullptr, 1);
    lora1_kernel<<<BT / 8, 256>>>(p_xw, dec_w1);
    lora2_kernel<<<BT / 8, 256>>>(dec_w2, p_w, tdecay, 0);

    // chunk-parallel WKV scan (decay + k-scale fused into phases)
    wkv_phase1<<<NCHUNK * NHEADS_TOT, 64>>>();
    wkv_combine<<<NHEADS_TOT, 256>>>(wkv0, out + BTC);
    wkv_phase3<<<NCHUNK * NHEADS_TOT, 64>>>();

    ln_kernel<<<BT, 256>>>(ln_g, ln_b);
    tf32_gemm<<<ggrid, 256, GSMEM>>>(p_xm, p_wo, out, BT, Cdim, Cdim);

    tail_kernel<<<16, 256>>>(x, out + BTC + BNHH);
}